// round 4
// baseline (speedup 1.0000x reference)
#include <cuda_runtime.h>

// ---------------------------------------------------------------------------
// ExtractNet (MMoE/PLE): 12 expert MLPs (256->64->64->64) + per-task softmax
// gates over 8 experts, gated combine. TF32 warp-mma implementation.
// ---------------------------------------------------------------------------

#define NE 12          // 8 task experts + 4 shared
#define IN_DIM 256
#define HID 64

// Packed weight scratch (allocation-free: __device__ globals)
__device__ float g_W1p[NE * IN_DIM * HID];   // 786KB  packed B-fragment layout
__device__ float g_W2p[NE * HID * HID];      // 196KB
__device__ float g_W3p[NE * HID * HID];      // 196KB
__device__ float g_Wgp[IN_DIM * 16];         // gates for both tasks, N=16
__device__ float g_b1[NE * HID];
__device__ float g_b2[NE * HID];
__device__ float g_b3[NE * HID];
__device__ float g_bg[16];

__device__ __forceinline__ unsigned f2tf32(float f) {
    unsigned u;
    asm("cvt.rna.tf32.f32 %0, %1;" : "=r"(u) : "f"(f));
    return u;
}

// m16n8k8 row.col tf32 mma.
// A frag: a0=(gy,gx) a1=(gy+8,gx) a2=(gy,gx+4) a3=(gy+8,gx+4)
// B frag: b0=(k=gx,n=gy) b1=(k=gx+4,n=gy)
// C frag: c0=(gy,2gx) c1=(gy,2gx+1) c2=(gy+8,2gx) c3=(gy+8,2gx+1)
__device__ __forceinline__ void mma8(float* c, const float4& a, const float2& b) {
    const unsigned* A = reinterpret_cast<const unsigned*>(&a);
    const unsigned* Bv = reinterpret_cast<const unsigned*>(&b);
    asm volatile(
        "mma.sync.aligned.m16n8k8.row.col.f32.tf32.tf32.f32 "
        "{%0,%1,%2,%3}, {%4,%5,%6,%7}, {%8,%9}, {%0,%1,%2,%3};\n"
        : "+f"(c[0]), "+f"(c[1]), "+f"(c[2]), "+f"(c[3])
        : "r"(A[0]), "r"(A[1]), "r"(A[2]), "r"(A[3]), "r"(Bv[0]), "r"(Bv[1]));
}

__device__ __forceinline__ void mma8u(float* c, unsigned a0, unsigned a1,
                                      unsigned a2, unsigned a3, const float2& b) {
    const unsigned* Bv = reinterpret_cast<const unsigned*>(&b);
    asm volatile(
        "mma.sync.aligned.m16n8k8.row.col.f32.tf32.tf32.f32 "
        "{%0,%1,%2,%3}, {%4,%5,%6,%7}, {%8,%9}, {%0,%1,%2,%3};\n"
        : "+f"(c[0]), "+f"(c[1]), "+f"(c[2]), "+f"(c[3])
        : "r"(a0), "r"(a1), "r"(a2), "r"(a3), "r"(Bv[0]), "r"(Bv[1]));
}

// ------------------------- weight packing kernels --------------------------
// Packed layout per expert: [kstep][ntile][lane][2] ; b0 = W[k0+lane%4][nt*8+lane/4],
// b1 = W[k0+4+lane%4][...]. Rounded to tf32.

__global__ void pack_w1(const float* __restrict__ wt, const float* __restrict__ ws) {
    int idx = blockIdx.x * blockDim.x + threadIdx.x;
    const int per = IN_DIM * HID;                 // 16384
    if (idx >= NE * per) return;
    int e = idx / per, pp = idx % per;
    int ks = pp >> 9;            // / (8 ntiles * 64)
    int rem = pp & 511;
    int nt = rem >> 6;
    int q = rem & 63;
    int lane = q >> 1, jb = q & 1;
    int k = ks * 8 + (lane & 3) + jb * 4;
    int n = nt * 8 + (lane >> 2);
    const float* src = (e < 8) ? (wt + e * per) : (ws + (e - 8) * per);
    g_W1p[idx] = __uint_as_float(f2tf32(src[k * HID + n]));
}

__global__ void pack_w23(const float* __restrict__ wt, const float* __restrict__ ws, int which) {
    int idx = blockIdx.x * blockDim.x + threadIdx.x;
    const int per = HID * HID;                    // 4096
    if (idx >= NE * per) return;
    int e = idx / per, pp = idx % per;
    int ks = pp >> 9;
    int rem = pp & 511;
    int nt = rem >> 6;
    int q = rem & 63;
    int lane = q >> 1, jb = q & 1;
    int k = ks * 8 + (lane & 3) + jb * 4;
    int n = nt * 8 + (lane >> 2);
    const float* src = (e < 8) ? (wt + e * per) : (ws + (e - 8) * per);
    float v = __uint_as_float(f2tf32(src[k * HID + n]));
    if (which) g_W3p[idx] = v; else g_W2p[idx] = v;
}

__global__ void pack_wg(const float* __restrict__ wg) {
    int idx = blockIdx.x * blockDim.x + threadIdx.x;    // 4096 total: K=256, N=16
    if (idx >= IN_DIM * 16) return;
    int ks = idx >> 7;           // / (2 ntiles * 64)
    int rem = idx & 127;
    int nt = rem >> 6;           // ntile == task (8 cols each)
    int q = rem & 63;
    int lane = q >> 1, jb = q & 1;
    int k = ks * 8 + (lane & 3) + jb * 4;
    int g = lane >> 2;           // col within task's 8 logits
    g_Wgp[idx] = __uint_as_float(f2tf32(wg[nt * (IN_DIM * 8) + k * 8 + g]));
}

__global__ void pack_bias(const float* bt1, const float* bs1,
                          const float* bt2, const float* bs2,
                          const float* bt3, const float* bs3,
                          const float* bg) {
    int i = blockIdx.x * blockDim.x + threadIdx.x;
    if (i < 768) g_b1[i] = (i < 512) ? bt1[i] : bs1[i - 512];
    else if (i < 1536) { int j = i - 768;  g_b2[j] = (j < 512) ? bt2[j] : bs2[j - 512]; }
    else if (i < 2304) { int j = i - 1536; g_b3[j] = (j < 512) ? bt3[j] : bs3[j - 512]; }
    else if (i < 2320) g_bg[i - 2304] = bg[i - 2304];
}

// ------------------------------ main kernel --------------------------------
// CTA: 64 rows of X. 8 warps = (mw = wid>>1) x (nw = wid&1); warp tile m16 x n32.
// Smem (floats):
//   Xp   [32][4][128]  16384   packed A fragments of X (tf32)
//   W1s  [32][8][64]   16384   packed B frags, one expert
//   W2s  [8][8][64]     4096
//   W3s  [8][8][64]     4096
//   hA   [64][68]       4352   layer-1 output (fp32, relu'd)
//   hB   [64][68]       4352   layer-2 output
//   gts  [64][17]       1088   gate probs (softmaxed)
//   outs aliases hA/hB region after expert loop: [64][128]
// total 50752 floats = 203008 bytes

#define SM_XP   0
#define SM_W1   16384
#define SM_W2   32768
#define SM_W3   36864
#define SM_HA   40960
#define SM_HB   45312
#define SM_GT   49664
#define SM_TOT  50752

__device__ __forceinline__ void store_relu(float* h, int r0, int nw, int gx,
                                           const float c[4][4], const float* bias) {
#pragma unroll
    for (int nt = 0; nt < 4; ++nt) {
        int col = nw * 32 + nt * 8 + 2 * gx;
        float b0 = bias[col], b1 = bias[col + 1];
        float2 lo = make_float2(fmaxf(c[nt][0] + b0, 0.f), fmaxf(c[nt][1] + b1, 0.f));
        float2 hi = make_float2(fmaxf(c[nt][2] + b0, 0.f), fmaxf(c[nt][3] + b1, 0.f));
        *reinterpret_cast<float2*>(h + r0 * 68 + col) = lo;
        *reinterpret_cast<float2*>(h + (r0 + 8) * 68 + col) = hi;
    }
}

__device__ __forceinline__ void gemm64(const float* __restrict__ hin,
                                       const float* __restrict__ Ws,
                                       int r0, int nw, int gx, int lane,
                                       float c[4][4]) {
#pragma unroll
    for (int ks = 0; ks < 8; ++ks) {
        int k0 = ks * 8 + gx;
        unsigned a0 = f2tf32(hin[r0 * 68 + k0]);
        unsigned a1 = f2tf32(hin[(r0 + 8) * 68 + k0]);
        unsigned a2 = f2tf32(hin[r0 * 68 + k0 + 4]);
        unsigned a3 = f2tf32(hin[(r0 + 8) * 68 + k0 + 4]);
#pragma unroll
        for (int nt = 0; nt < 4; ++nt) {
            const float2 b = *reinterpret_cast<const float2*>(
                Ws + ((ks * 8 + nw * 4 + nt) << 6) + (lane << 1));
            mma8u(c[nt], a0, a1, a2, a3, b);
        }
    }
}

__global__ __launch_bounds__(256, 1)
void moe_main(const float* __restrict__ X, float* __restrict__ out) {
    extern __shared__ float smem[];
    float* Xp  = smem + SM_XP;
    float* W1s = smem + SM_W1;
    float* W2s = smem + SM_W2;
    float* W3s = smem + SM_W3;
    float* hA  = smem + SM_HA;
    float* hB  = smem + SM_HB;
    float* gts = smem + SM_GT;
    float* outs = smem + SM_HA;   // alias, used only after expert loop

    const int tid = threadIdx.x;
    const int wid = tid >> 5;
    const int lane = tid & 31;
    const int gy = lane >> 2, gx = lane & 3;
    const int mw = wid >> 1;      // 0..3
    const int nw = wid & 1;       // 0..1
    const int rowbase = blockIdx.x * 64;
    const int r0 = mw * 16 + gy;

    // 1. load X tile, round to tf32, store in packed A-fragment layout
#pragma unroll
    for (int it = 0; it < 16; ++it) {
        int g = tid + it * 256;        // float4 id, 4096 total
        int r = g >> 6;
        int c = (g & 63) << 2;
        float4 v = *reinterpret_cast<const float4*>(
            X + (size_t)(rowbase + r) * IN_DIM + c);
        int ks = c >> 3;
        int mt = r >> 4;
        int rp = r & 15;
        int j = (rp >> 3) + (((c & 7) >= 4) ? 2 : 0);
        float* p = Xp + ((ks * 4 + mt) << 7) + ((rp & 7) << 4) + j;
        p[0]  = __uint_as_float(f2tf32(v.x));
        p[4]  = __uint_as_float(f2tf32(v.y));
        p[8]  = __uint_as_float(f2tf32(v.z));
        p[12] = __uint_as_float(f2tf32(v.w));
    }
    __syncthreads();

    // 2. gate logits via mma: warp (mw,nw) -> rows mw*16.., cols nw*8..
    {
        float c[4] = {0.f, 0.f, 0.f, 0.f};
#pragma unroll 8
        for (int ks = 0; ks < 32; ++ks) {
            float4 a4 = *reinterpret_cast<const float4*>(
                Xp + ((ks * 4 + mw) << 7) + (lane << 2));
            float2 b2 = *reinterpret_cast<const float2*>(
                g_Wgp + ((ks * 2 + nw) << 6) + (lane << 1));
            mma8(c, a4, b2);
        }
        int col = nw * 8 + 2 * gx;
        gts[r0 * 17 + col]           = c[0] + g_bg[col];
        gts[r0 * 17 + col + 1]       = c[1] + g_bg[col + 1];
        gts[(r0 + 8) * 17 + col]     = c[2] + g_bg[col];
        gts[(r0 + 8) * 17 + col + 1] = c[3] + g_bg[col + 1];
    }
    __syncthreads();

    // 3. softmax per (row, task) over 8 logits
    if (tid < 128) {
        int r = tid >> 1, t = tid & 1;
        float* p = gts + r * 17 + t * 8;
        float m = p[0];
#pragma unroll
        for (int i = 1; i < 8; ++i) m = fmaxf(m, p[i]);
        float e[8]; float s = 0.f;
#pragma unroll
        for (int i = 0; i < 8; ++i) { e[i] = __expf(p[i] - m); s += e[i]; }
        float inv = 1.f / s;
#pragma unroll
        for (int i = 0; i < 8; ++i) p[i] = e[i] * inv;
    }

    float acc[2][16];
#pragma unroll
    for (int i = 0; i < 32; ++i) (&acc[0][0])[i] = 0.f;

    // 4. expert loop
    for (int e = 0; e < NE; ++e) {
        __syncthreads();
        // stage this expert's packed weights
        {
            const float4* s1 = reinterpret_cast<const float4*>(g_W1p + e * 16384);
            float4* d1 = reinterpret_cast<float4*>(W1s);
#pragma unroll
            for (int it = 0; it < 16; ++it) d1[tid + it * 256] = s1[tid + it * 256];
            const float4* s2 = reinterpret_cast<const float4*>(g_W2p + e * 4096);
            float4* d2 = reinterpret_cast<float4*>(W2s);
#pragma unroll
            for (int it = 0; it < 4; ++it) d2[tid + it * 256] = s2[tid + it * 256];
            const float4* s3 = reinterpret_cast<const float4*>(g_W3p + e * 4096);
            float4* d3 = reinterpret_cast<float4*>(W3s);
#pragma unroll
            for (int it = 0; it < 4; ++it) d3[tid + it * 256] = s3[tid + it * 256];
        }
        __syncthreads();

        // L1: [64,256] x [256,64]
        {
            float c[4][4] = {};
#pragma unroll 8
            for (int ks = 0; ks < 32; ++ks) {
                float4 a4 = *reinterpret_cast<const float4*>(
                    Xp + ((ks * 4 + mw) << 7) + (lane << 2));
#pragma unroll
                for (int nt = 0; nt < 4; ++nt) {
                    const float2 b = *reinterpret_cast<const float2*>(
                        W1s + ((ks * 8 + nw * 4 + nt) << 6) + (lane << 1));
                    mma8(c[nt], a4, b);
                }
            }
            store_relu(hA, r0, nw, gx, c, g_b1 + e * 64);
        }
        __syncthreads();

        // L2
        {
            float c[4][4] = {};
            gemm64(hA, W2s, r0, nw, gx, lane, c);
            store_relu(hB, r0, nw, gx, c, g_b2 + e * 64);
        }
        __syncthreads();

        // L3 + gated accumulate (no relu)
        {
            float c[4][4] = {};
            gemm64(hB, W3s, r0, nw, gx, lane, c);
            const float* b3 = g_b3 + e * 64;
            if (e < 8) {
                int t = e >> 2, gi = e & 3;
                float g0 = gts[r0 * 17 + t * 8 + gi];
                float g1 = gts[(r0 + 8) * 17 + t * 8 + gi];
#pragma unroll
                for (int nt = 0; nt < 4; ++nt) {
                    int col = nw * 32 + nt * 8 + 2 * gx;
                    float b0 = b3[col], b1 = b3[col + 1];
                    acc[t][nt * 4 + 0] += g0 * (c[nt][0] + b0);
                    acc[t][nt * 4 + 1] += g0 * (c[nt][1] + b1);
                    acc[t][nt * 4 + 2] += g1 * (c[nt][2] + b0);
                    acc[t][nt * 4 + 3] += g1 * (c[nt][3] + b1);
                }
            } else {
                int gi = 4 + (e - 8);
                float ga0 = gts[r0 * 17 + gi],     ga1 = gts[(r0 + 8) * 17 + gi];
                float gb0 = gts[r0 * 17 + 8 + gi], gb1 = gts[(r0 + 8) * 17 + 8 + gi];
#pragma unroll
                for (int nt = 0; nt < 4; ++nt) {
                    int col = nw * 32 + nt * 8 + 2 * gx;
                    float b0 = b3[col], b1 = b3[col + 1];
                    float v0 = c[nt][0] + b0, v1 = c[nt][1] + b1;
                    float v2 = c[nt][2] + b0, v3 = c[nt][3] + b1;
                    acc[0][nt * 4 + 0] += ga0 * v0; acc[1][nt * 4 + 0] += gb0 * v0;
                    acc[0][nt * 4 + 1] += ga0 * v1; acc[1][nt * 4 + 1] += gb0 * v1;
                    acc[0][nt * 4 + 2] += ga1 * v2; acc[1][nt * 4 + 2] += gb1 * v2;
                    acc[0][nt * 4 + 3] += ga1 * v3; acc[1][nt * 4 + 3] += gb1 * v3;
                }
            }
        }
    }
    __syncthreads();

    // 5. stage to smem, coalesced store. out layout: [B][T=2][64]
#pragma unroll
    for (int t = 0; t < 2; ++t)
#pragma unroll
        for (int nt = 0; nt < 4; ++nt) {
            int col = t * 64 + nw * 32 + nt * 8 + 2 * gx;
            *reinterpret_cast<float2*>(outs + r0 * 128 + col) =
                make_float2(acc[t][nt * 4 + 0], acc[t][nt * 4 + 1]);
            *reinterpret_cast<float2*>(outs + (r0 + 8) * 128 + col) =
                make_float2(acc[t][nt * 4 + 2], acc[t][nt * 4 + 3]);
        }
    __syncthreads();
    {
        float4* dst = reinterpret_cast<float4*>(out + (size_t)rowbase * 128);
        const float4* srcp = reinterpret_cast<const float4*>(outs);
#pragma unroll
        for (int it = 0; it < 8; ++it) dst[tid + it * 256] = srcp[tid + it * 256];
    }
}

// ------------------------------- launcher ----------------------------------
extern "C" void kernel_launch(void* const* d_in, const int* in_sizes, int n_in,
                              void* d_out, int out_size) {
    const float* X   = (const float*)d_in[0];
    const float* Wt1 = (const float*)d_in[1];
    const float* bt1 = (const float*)d_in[2];
    const float* Wt2 = (const float*)d_in[3];
    const float* bt2 = (const float*)d_in[4];
    const float* Wt3 = (const float*)d_in[5];
    const float* bt3 = (const float*)d_in[6];
    const float* Ws1 = (const float*)d_in[7];
    const float* bs1 = (const float*)d_in[8];
    const float* Ws2 = (const float*)d_in[9];
    const float* bs2 = (const float*)d_in[10];
    const float* Ws3 = (const float*)d_in[11];
    const float* bs3 = (const float*)d_in[12];
    const float* Wg  = (const float*)d_in[13];
    const float* bg  = (const float*)d_in[14];
    float* out = (float*)d_out;

    // pack weights (tiny, every call; deterministic)
    pack_w1<<<(NE * IN_DIM * HID + 255) / 256, 256>>>(Wt1, Ws1);
    pack_w23<<<(NE * HID * HID + 255) / 256, 256>>>(Wt2, Ws2, 0);
    pack_w23<<<(NE * HID * HID + 255) / 256, 256>>>(Wt3, Ws3, 1);
    pack_wg<<<(IN_DIM * 16 + 255) / 256, 256>>>(Wg);
    pack_bias<<<10, 256>>>(bt1, bs1, bt2, bs2, bt3, bs3, bg);

    cudaFuncSetAttribute(moe_main, cudaFuncAttributeMaxDynamicSharedMemorySize,
                         SM_TOT * (int)sizeof(float));
    moe_main<<<65536 / 64, 256, SM_TOT * sizeof(float)>>>(X, out);
}

// round 6
// speedup vs baseline: 2.6967x; 2.6967x over previous
#include <cuda_runtime.h>
#include <cuda_fp16.h>
#include <cstdint>

// ---------------------------------------------------------------------------
// ExtractNet (MMoE/PLE): 12 expert MLPs (256->64->64->64) + per-task softmax
// gates. fp16 mma.sync.m16n8k16, fp32 accum. 64 rows/CTA, 8 warps, 2 CTA/SM.
// ---------------------------------------------------------------------------

#define NE 12

// Packed weights: u32 = half2 in exact B-fragment order
__device__ unsigned g_W1p[NE * 8192];   // per expert: 16ks x 8nt x 64
__device__ unsigned g_W2p[NE * 2048];   // 4ks x 8nt x 64
__device__ unsigned g_W3p[NE * 2048];
__device__ unsigned g_Wgp[2048];        // gates: 16ks x 2slot x 64
__device__ float g_b1[NE * 64];
__device__ float g_b2[NE * 64];
__device__ float g_b3[NE * 64];
__device__ float g_bg[16];

__device__ __forceinline__ unsigned packh2(float a, float b) {
    __half2 h = __floats2half2_rn(a, b);
    return *reinterpret_cast<unsigned*>(&h);
}

__device__ __forceinline__ uint32_t smem_to_u32(const void* p) {
    uint32_t a;
    asm("{ .reg .u64 t; cvta.to.shared.u64 t, %1; cvt.u32.u64 %0, t; }"
        : "=r"(a) : "l"(p));
    return a;
}

// m16n8k16 fp16 mma, fp32 accum.
// lane = gy*4+gx (gy=lane>>2, gx=lane&3)
// A: a0={A[gy][2gx],A[gy][2gx+1]} a1={A[gy+8][..]} a2={A[gy][2gx+8],..} a3={A[gy+8][2gx+8],..}
// B: b0={B[2gx][gy],B[2gx+1][gy]} b1={B[2gx+8][gy],B[2gx+9][gy]}
// C: c0=(gy,2gx) c1=(gy,2gx+1) c2=(gy+8,2gx) c3=(gy+8,2gx+1)
__device__ __forceinline__ void mma16(float c[4], unsigned a0, unsigned a1,
                                      unsigned a2, unsigned a3,
                                      unsigned b0, unsigned b1) {
    asm volatile(
        "mma.sync.aligned.m16n8k16.row.col.f32.f16.f16.f32 "
        "{%0,%1,%2,%3}, {%4,%5,%6,%7}, {%8,%9}, {%0,%1,%2,%3};\n"
        : "+f"(c[0]), "+f"(c[1]), "+f"(c[2]), "+f"(c[3])
        : "r"(a0), "r"(a1), "r"(a2), "r"(a3), "r"(b0), "r"(b1));
}

__device__ __forceinline__ void cp16(uint32_t dst, const void* src) {
    asm volatile("cp.async.cg.shared.global [%0], [%1], 16;" :: "r"(dst), "l"(src));
}
#define CP_COMMIT() asm volatile("cp.async.commit_group;" ::: "memory")
#define CP_WAIT0()  asm volatile("cp.async.wait_group 0;" ::: "memory")

// ------------------------- weight packing kernels --------------------------
// Dest u32 index within expert: (ks*NT + nt)*64 + lane*2 + j
// value = half2( W[k0][n], W[k0+1][n] ), k0 = ks*16 + j*8 + 2gx, n = nt*8 + gy

__global__ void pack_w1(const float* __restrict__ wt, const float* __restrict__ ws) {
    int idx = blockIdx.x * blockDim.x + threadIdx.x;
    if (idx >= NE * 8192) return;
    int e = idx >> 13, p = idx & 8191;
    int ks = p >> 9, rem = p & 511, nt = rem >> 6, q = rem & 63;
    int lane = q >> 1, j = q & 1;
    int gy = lane >> 2, gx = lane & 3;
    int k0 = ks * 16 + j * 8 + 2 * gx, n = nt * 8 + gy;
    const float* src = (e < 8) ? wt + e * 16384 : ws + (e - 8) * 16384;
    g_W1p[idx] = packh2(src[k0 * 64 + n], src[(k0 + 1) * 64 + n]);
}

__global__ void pack_w23(const float* __restrict__ wt, const float* __restrict__ ws,
                         int which) {
    int idx = blockIdx.x * blockDim.x + threadIdx.x;
    if (idx >= NE * 2048) return;
    int e = idx >> 11, p = idx & 2047;
    int ks = p >> 9, rem = p & 511, nt = rem >> 6, q = rem & 63;
    int lane = q >> 1, j = q & 1;
    int gy = lane >> 2, gx = lane & 3;
    int k0 = ks * 16 + j * 8 + 2 * gx, n = nt * 8 + gy;
    const float* src = (e < 8) ? wt + e * 4096 : ws + (e - 8) * 4096;
    unsigned v = packh2(src[k0 * 64 + n], src[(k0 + 1) * 64 + n]);
    if (which) g_W3p[idx] = v; else g_W2p[idx] = v;
}

__global__ void pack_wg(const float* __restrict__ wg) {
    int idx = blockIdx.x * blockDim.x + threadIdx.x;
    if (idx >= 2048) return;
    int ks = idx >> 7, rem = idx & 127, t = rem >> 6, q = rem & 63;
    int lane = q >> 1, j = q & 1;
    int gy = lane >> 2, gx = lane & 3;
    int k0 = ks * 16 + j * 8 + 2 * gx;
    g_Wgp[idx] = packh2(wg[t * 2048 + k0 * 8 + gy], wg[t * 2048 + (k0 + 1) * 8 + gy]);
}

__global__ void pack_bias(const float* bt1, const float* bs1,
                          const float* bt2, const float* bs2,
                          const float* bt3, const float* bs3, const float* bg) {
    int i = blockIdx.x * blockDim.x + threadIdx.x;
    if (i < 768) g_b1[i] = (i < 512) ? bt1[i] : bs1[i - 512];
    else if (i < 1536) { int j = i - 768;  g_b2[j] = (j < 512) ? bt2[j] : bs2[j - 512]; }
    else if (i < 2304) { int j = i - 1536; g_b3[j] = (j < 512) ? bt3[j] : bs3[j - 512]; }
    else if (i < 2320) g_bg[i - 2304] = bg[i - 2304];
}

// ------------------------------ main kernel --------------------------------
// smem u32 offsets
#define U_XP 0        // 8192: X packed A-frags (16ks x 4mt x 128), lane-rotated
#define U_W1 8192     // 8192 (single buffer; out-staging after loop)
#define U_W2 16384    // 2048 (single)
#define U_W3 18432    // 2 x 2048 (double)
#define U_HA 22528    // 2048 (aliases Wg during gate phase)
#define U_HB 24576    // 2048
#define U_GT 26624    // 1088 floats (gate probs, stride 17)
#define U_TOT 27712   // 110,848 B -> 2 CTAs/SM

__device__ __forceinline__ unsigned xp_idx4(int blk, int lane) {
    return blk * 128 + (((lane + blk * 4) & 31) << 2);
}

__global__ __launch_bounds__(256, 2)
void moe_main(const float* __restrict__ X, float* __restrict__ out) {
    extern __shared__ unsigned sm[];
    const int tid = threadIdx.x, wid = tid >> 5, lane = tid & 31;
    const int gy = lane >> 2, gx = lane & 3;
    const int mw = wid >> 1, nw = wid & 1;
    const int r0 = mw * 16 + gy;
    const size_t rowbase = (size_t)blockIdx.x * 64;

    unsigned* Xp  = sm + U_XP;
    unsigned* W1s = sm + U_W1;
    unsigned* W2s = sm + U_W2;
    unsigned* W3s = sm + U_W3;
    unsigned* Wg  = sm + U_HA;   // alias: gates done before hA first written
    unsigned* hA  = sm + U_HA;
    unsigned* hB  = sm + U_HB;
    float* gts = reinterpret_cast<float*>(sm + U_GT);
    const uint32_t sb = smem_to_u32(sm);

    // ---- initial prefetch: W1[0], W2[0], W3[0]->buf0, Wg ----
    {
        const uint4* s1 = reinterpret_cast<const uint4*>(g_W1p);
#pragma unroll
        for (int i = 0; i < 8; ++i)
            cp16(sb + (U_W1 << 2) + (tid + i * 256) * 16, s1 + tid + i * 256);
        const uint4* s2 = reinterpret_cast<const uint4*>(g_W2p);
#pragma unroll
        for (int i = 0; i < 2; ++i)
            cp16(sb + (U_W2 << 2) + (tid + i * 256) * 16, s2 + tid + i * 256);
        const uint4* s3 = reinterpret_cast<const uint4*>(g_W3p);
#pragma unroll
        for (int i = 0; i < 2; ++i)
            cp16(sb + (U_W3 << 2) + (tid + i * 256) * 16, s3 + tid + i * 256);
        const uint4* sg = reinterpret_cast<const uint4*>(g_Wgp);
#pragma unroll
        for (int i = 0; i < 2; ++i)
            cp16(sb + (U_HA << 2) + (tid + i * 256) * 16, sg + tid + i * 256);
        CP_COMMIT();
    }

    // ---- stage X: gmem (coalesced float4) -> packed fp16 A-frags ----
    {
        const float4* xg = reinterpret_cast<const float4*>(X + rowbase * 256);
#pragma unroll
        for (int it = 0; it < 16; ++it) {
            int g = tid + it * 256;              // float4 id, row-major
            float4 v = xg[g];
            int r = g >> 6, c4 = g & 63;
            int ks = c4 >> 2, kk = (c4 & 3) * 4; // kk in {0,4,8,12}
            int mt = r >> 4, rl = r & 15;
            int jr = (rl >= 8) ? 1 : 0, gyy = rl & 7;
            int gxp = (kk & 7) >> 1;             // 0 or 2
            int j0 = jr + ((kk & 8) ? 2 : 0);
            int blk = ks * 4 + mt;
            int fl0 = gyy * 4 + gxp;
            Xp[blk * 128 + (((fl0     + blk * 4) & 31) << 2) + j0] = packh2(v.x, v.y);
            Xp[blk * 128 + (((fl0 + 1 + blk * 4) & 31) << 2) + j0] = packh2(v.z, v.w);
        }
    }
    CP_WAIT0();
    __syncthreads();

    // ---- gate logits via mma: warp (mw,nw) -> rows mw*16.., cols nw*8.. ----
    {
        float c[4] = {0.f, 0.f, 0.f, 0.f};
#pragma unroll
        for (int ks = 0; ks < 16; ++ks) {
            int blk = ks * 4 + mw;
            uint4 A = *reinterpret_cast<const uint4*>(Xp + xp_idx4(blk, lane));
            uint2 B = *reinterpret_cast<const uint2*>(Wg + (ks * 2 + nw) * 64 + lane * 2);
            mma16(c, A.x, A.y, A.z, A.w, B.x, B.y);
        }
        int col = nw * 8 + 2 * gx;
        gts[r0 * 17 + col]           = c[0] + g_bg[col];
        gts[r0 * 17 + col + 1]       = c[1] + g_bg[col + 1];
        gts[(r0 + 8) * 17 + col]     = c[2] + g_bg[col];
        gts[(r0 + 8) * 17 + col + 1] = c[3] + g_bg[col + 1];
    }
    __syncthreads();

    // ---- softmax per (row, task) over 8 logits ----
    if (tid < 128) {
        int r = tid >> 1, t = tid & 1;
        float* p = gts + r * 17 + t * 8;
        float m = p[0];
#pragma unroll
        for (int i = 1; i < 8; ++i) m = fmaxf(m, p[i]);
        float e8[8]; float s = 0.f;
#pragma unroll
        for (int i = 0; i < 8; ++i) { e8[i] = __expf(p[i] - m); s += e8[i]; }
        float inv = 1.f / s;
#pragma unroll
        for (int i = 0; i < 8; ++i) p[i] = e8[i] * inv;
    }
    // gts visible to all by the post-L1 __syncthreads of expert 0.

    float acc0[16], acc1[16];
#pragma unroll
    for (int i = 0; i < 16; ++i) { acc0[i] = 0.f; acc1[i] = 0.f; }

    // ---- expert loop ----
    for (int e = 0; e < NE; ++e) {
        if (e) { CP_WAIT0(); __syncthreads(); }   // W1/W2/W3[e] ready+visible
        const unsigned* W3cur = W3s + (e & 1) * 2048;

        // L1: [64,256] x W1^T, K=256 -> 16 ksteps
        float c1[4][4] = {};
#pragma unroll
        for (int ks = 0; ks < 16; ++ks) {
            int blk = ks * 4 + mw;
            uint4 A = *reinterpret_cast<const uint4*>(Xp + xp_idx4(blk, lane));
#pragma unroll
            for (int nt = 0; nt < 4; ++nt) {
                uint2 B = *reinterpret_cast<const uint2*>(
                    W1s + (ks * 8 + nw * 4 + nt) * 64 + lane * 2);
                mma16(c1[nt], A.x, A.y, A.z, A.w, B.x, B.y);
            }
        }
        // epilogue 1: bias+relu -> hA in packed A-frag layout (STS.64/lane)
        {
            const float* b = g_b1 + e * 64;
#pragma unroll
            for (int nt = 0; nt < 4; ++nt) {
                int col = nw * 32 + nt * 8 + 2 * gx;
                float b0 = b[col], b1v = b[col + 1];
                unsigned lo = packh2(fmaxf(c1[nt][0] + b0, 0.f), fmaxf(c1[nt][1] + b1v, 0.f));
                unsigned hi = packh2(fmaxf(c1[nt][2] + b0, 0.f), fmaxf(c1[nt][3] + b1v, 0.f));
                int ksp = (nw * 4 + nt) >> 1, jb = (nt & 1) * 2;
                *reinterpret_cast<uint2*>(hA + (ksp * 4 + mw) * 128 + lane * 4 + jb) =
                    make_uint2(lo, hi);
            }
        }
        __syncthreads();                    // hA visible; W1s free
        if (e + 1 < NE) {
            const uint4* s1 = reinterpret_cast<const uint4*>(g_W1p) + (e + 1) * 2048;
#pragma unroll
            for (int i = 0; i < 8; ++i)
                cp16(sb + (U_W1 << 2) + (tid + i * 256) * 16, s1 + tid + i * 256);
        }
        CP_COMMIT();

        // L2: K=64 -> 4 ksteps
        float c2[4][4] = {};
#pragma unroll
        for (int ks = 0; ks < 4; ++ks) {
            uint4 A = *reinterpret_cast<const uint4*>(hA + (ks * 4 + mw) * 128 + lane * 4);
#pragma unroll
            for (int nt = 0; nt < 4; ++nt) {
                uint2 B = *reinterpret_cast<const uint2*>(
                    W2s + (ks * 8 + nw * 4 + nt) * 64 + lane * 2);
                mma16(c2[nt], A.x, A.y, A.z, A.w, B.x, B.y);
            }
        }
        {
            const float* b = g_b2 + e * 64;
#pragma unroll
            for (int nt = 0; nt < 4; ++nt) {
                int col = nw * 32 + nt * 8 + 2 * gx;
                float b0 = b[col], b1v = b[col + 1];
                unsigned lo = packh2(fmaxf(c2[nt][0] + b0, 0.f), fmaxf(c2[nt][1] + b1v, 0.f));
                unsigned hi = packh2(fmaxf(c2[nt][2] + b0, 0.f), fmaxf(c2[nt][3] + b1v, 0.f));
                int ksp = (nw * 4 + nt) >> 1, jb = (nt & 1) * 2;
                *reinterpret_cast<uint2*>(hB + (ksp * 4 + mw) * 128 + lane * 4 + jb) =
                    make_uint2(lo, hi);
            }
        }
        __syncthreads();                    // hB visible; W2s free
        if (e + 1 < NE) {
            const uint4* s2 = reinterpret_cast<const uint4*>(g_W2p) + (e + 1) * 512;
#pragma unroll
            for (int i = 0; i < 2; ++i)
                cp16(sb + (U_W2 << 2) + (tid + i * 256) * 16, s2 + tid + i * 256);
            const uint4* s3 = reinterpret_cast<const uint4*>(g_W3p) + (e + 1) * 512;
            uint32_t d3 = sb + ((U_W3 + ((e + 1) & 1) * 2048) << 2);
#pragma unroll
            for (int i = 0; i < 2; ++i)
                cp16(d3 + (tid + i * 256) * 16, s3 + tid + i * 256);
        }
        CP_COMMIT();

        // L3
        float c3[4][4] = {};
#pragma unroll
        for (int ks = 0; ks < 4; ++ks) {
            uint4 A = *reinterpret_cast<const uint4*>(hB + (ks * 4 + mw) * 128 + lane * 4);
#pragma unroll
            for (int nt = 0; nt < 4; ++nt) {
                uint2 B = *reinterpret_cast<const uint2*>(
                    W3cur + (ks * 8 + nw * 4 + nt) * 64 + lane * 2);
                mma16(c3[nt], A.x, A.y, A.z, A.w, B.x, B.y);
            }
        }
        // epilogue 3: bias + gated accumulate into registers
        {
            const float* b = g_b3 + e * 64;
            if (e < 8) {
                int t = e >> 2, gi = e & 3;
                float g0 = gts[r0 * 17 + t * 8 + gi];
                float g1 = gts[(r0 + 8) * 17 + t * 8 + gi];
                if (e < 4) {
#pragma unroll
                    for (int nt = 0; nt < 4; ++nt) {
                        int col = nw * 32 + nt * 8 + 2 * gx;
                        float b0 = b[col], b1v = b[col + 1];
                        acc0[nt * 4 + 0] += g0 * (c3[nt][0] + b0);
                        acc0[nt * 4 + 1] += g0 * (c3[nt][1] + b1v);
                        acc0[nt * 4 + 2] += g1 * (c3[nt][2] + b0);
                        acc0[nt * 4 + 3] += g1 * (c3[nt][3] + b1v);
                    }
                } else {
#pragma unroll
                    for (int nt = 0; nt < 4; ++nt) {
                        int col = nw * 32 + nt * 8 + 2 * gx;
                        float b0 = b[col], b1v = b[col + 1];
                        acc1[nt * 4 + 0] += g0 * (c3[nt][0] + b0);
                        acc1[nt * 4 + 1] += g0 * (c3[nt][1] + b1v);
                        acc1[nt * 4 + 2] += g1 * (c3[nt][2] + b0);
                        acc1[nt * 4 + 3] += g1 * (c3[nt][3] + b1v);
                    }
                }
            } else {
                float ga0 = gts[r0 * 17 + (e - 4)];
                float ga1 = gts[(r0 + 8) * 17 + (e - 4)];
                float gb0 = gts[r0 * 17 + (e + 4)];
                float gb1 = gts[(r0 + 8) * 17 + (e + 4)];
#pragma unroll
                for (int nt = 0; nt < 4; ++nt) {
                    int col = nw * 32 + nt * 8 + 2 * gx;
                    float b0 = b[col], b1v = b[col + 1];
                    float v0 = c3[nt][0] + b0, v1 = c3[nt][1] + b1v;
                    float v2 = c3[nt][2] + b0, v3 = c3[nt][3] + b1v;
                    acc0[nt * 4 + 0] += ga0 * v0; acc1[nt * 4 + 0] += gb0 * v0;
                    acc0[nt * 4 + 1] += ga0 * v1; acc1[nt * 4 + 1] += gb0 * v1;
                    acc0[nt * 4 + 2] += ga1 * v2; acc1[nt * 4 + 2] += gb1 * v2;
                    acc0[nt * 4 + 3] += ga1 * v3; acc1[nt * 4 + 3] += gb1 * v3;
                }
            }
        }
    }

    __syncthreads();
    // ---- output: stage fp32 to smem (stride 132), then coalesced float4 ----
    {
        float* ost = reinterpret_cast<float*>(sm + U_W1);
#pragma unroll
        for (int nt = 0; nt < 4; ++nt) {
            int col0 = nw * 32 + nt * 8 + 2 * gx;          // task 0
            *reinterpret_cast<float2*>(ost + r0 * 132 + col0) =
                make_float2(acc0[nt * 4 + 0], acc0[nt * 4 + 1]);
            *reinterpret_cast<float2*>(ost + (r0 + 8) * 132 + col0) =
                make_float2(acc0[nt * 4 + 2], acc0[nt * 4 + 3]);
            int col1 = 64 + col0;                          // task 1
            *reinterpret_cast<float2*>(ost + r0 * 132 + col1) =
                make_float2(acc1[nt * 4 + 0], acc1[nt * 4 + 1]);
            *reinterpret_cast<float2*>(ost + (r0 + 8) * 132 + col1) =
                make_float2(acc1[nt * 4 + 2], acc1[nt * 4 + 3]);
        }
    }
    __syncthreads();
    {
        float4* og = reinterpret_cast<float4*>(out + rowbase * 128);
        const float* ost = reinterpret_cast<const float*>(sm + U_W1);
#pragma unroll
        for (int it = 0; it < 8; ++it) {
            int g = tid + it * 256;
            int rr = g >> 5, q = g & 31;
            og[g] = *reinterpret_cast<const float4*>(ost + rr * 132 + q * 4);
        }
    }
}

// ------------------------------- launcher ----------------------------------
extern "C" void kernel_launch(void* const* d_in, const int* in_sizes, int n_in,
                              void* d_out, int out_size) {
    const float* X   = (const float*)d_in[0];
    const float* Wt1 = (const float*)d_in[1];
    const float* bt1 = (const float*)d_in[2];
    const float* Wt2 = (const float*)d_in[3];
    const float* bt2 = (const float*)d_in[4];
    const float* Wt3 = (const float*)d_in[5];
    const float* bt3 = (const float*)d_in[6];
    const float* Ws1 = (const float*)d_in[7];
    const float* bs1 = (const float*)d_in[8];
    const float* Ws2 = (const float*)d_in[9];
    const float* bs2 = (const float*)d_in[10];
    const float* Ws3 = (const float*)d_in[11];
    const float* bs3 = (const float*)d_in[12];
    const float* Wg  = (const float*)d_in[13];
    const float* bg  = (const float*)d_in[14];
    float* out = (float*)d_out;

    pack_w1<<<(NE * 8192 + 255) / 256, 256>>>(Wt1, Ws1);
    pack_w23<<<(NE * 2048 + 255) / 256, 256>>>(Wt2, Ws2, 0);
    pack_w23<<<(NE * 2048 + 255) / 256, 256>>>(Wt3, Ws3, 1);
    pack_wg<<<8, 256>>>(Wg);
    pack_bias<<<10, 256>>>(bt1, bs1, bt2, bs2, bt3, bs3, bg);

    cudaFuncSetAttribute(moe_main, cudaFuncAttributeMaxDynamicSharedMemorySize,
                         U_TOT * (int)sizeof(unsigned));
    moe_main<<<65536 / 64, 256, U_TOT * sizeof(unsigned)>>>(X, out);
}